// round 1
// baseline (speedup 1.0000x reference)
#include <cuda_runtime.h>
#include <math.h>

// Problem constants (fixed shapes from reference)
#define L_SEQ   8192
#define BATCH   4
#define DMODEL  1024
#define NHEADS  16
#define DH      64
#define MROWS   (BATCH * L_SEQ)      // 32768
#define NQKV    (3 * DMODEL)         // 3072
#define EPSV    1e-6f
#define NCHUNK  8                    // L-split chunks for kv reduction

// ------------------------------------------------------------------
// Scratch (device globals; no allocation allowed in kernel_launch)
// ------------------------------------------------------------------
__device__ float g_qkv[(size_t)MROWS * NQKV];            // phi(q) | phi(k)*m | v*m
__device__ float g_y[(size_t)MROWS * DMODEL];            // attention output pre-Wout
__device__ float g_kv_part[NCHUNK][BATCH * NHEADS][DH][DH];
__device__ float g_ksum_part[NCHUNK][BATCH * NHEADS][DH];
__device__ float g_kv[BATCH * NHEADS][DH][DH];
__device__ float g_ksum[BATCH * NHEADS][DH];

__device__ __forceinline__ float phi_f(float z) {
    // elu(z)+1 : z>0 ? z+1 : exp(z)
    return z > 0.0f ? z + 1.0f : __expf(z);
}

// ------------------------------------------------------------------
// SGEMM: C[M,N] = A[M,K] @ B[K,N], row-major, M%128==0, N%128==0, K%16==0
// EPI 0: qkv epilogue  (cols [0,1024): phi ; [1024,2048): phi*mask ; [2048,3072): *mask)
// EPI 1: out epilogue  (*mask[row])
// 128x128 tile, 256 threads, 8x8 per thread, BK=16, double-buffered smem.
// ------------------------------------------------------------------
template <int EPI>
__global__ __launch_bounds__(256)
void sgemm_kernel(const float* __restrict__ A, const float* __restrict__ B,
                  float* __restrict__ C, int M, int N, int K,
                  const int* __restrict__ mask)
{
    __shared__ float As[2][16][128];
    __shared__ float Bs[2][16][128];

    const int tid = threadIdx.x;
    const int tx  = tid & 15;          // N-dim thread coord (0..15)
    const int ty  = tid >> 4;          // M-dim thread coord (0..15)
    const int bm  = blockIdx.y * 128;
    const int bn  = blockIdx.x * 128;

    // A tile: 128 rows x 16 cols = 512 float4; thread loads f=tid and f=tid+256
    const int aRow = tid >> 2;            // 0..63 (+64 for second)
    const int aCol = (tid & 3) << 2;      // 0,4,8,12
    // B tile: 16 rows x 128 cols = 512 float4
    const int bRow = tid >> 5;            // 0..7 (+8 for second)
    const int bCol = (tid & 31) << 2;     // 0..124

    const float* Ap = A + (size_t)(bm + aRow) * K + aCol;
    const float* Bp = B + (size_t)bRow * N + bn + bCol;

    float4 a0 = *(const float4*)Ap;
    float4 a1 = *(const float4*)(Ap + (size_t)64 * K);
    float4 b0 = *(const float4*)Bp;
    float4 b1 = *(const float4*)(Bp + (size_t)8 * N);

    // store tile 0 (A transposed into [k][m])
    As[0][aCol + 0][aRow]      = a0.x;
    As[0][aCol + 1][aRow]      = a0.y;
    As[0][aCol + 2][aRow]      = a0.z;
    As[0][aCol + 3][aRow]      = a0.w;
    As[0][aCol + 0][64 + aRow] = a1.x;
    As[0][aCol + 1][64 + aRow] = a1.y;
    As[0][aCol + 2][64 + aRow] = a1.z;
    As[0][aCol + 3][64 + aRow] = a1.w;
    *(float4*)&Bs[0][bRow][bCol]     = b0;
    *(float4*)&Bs[0][8 + bRow][bCol] = b1;
    __syncthreads();

    float acc[8][8];
    #pragma unroll
    for (int i = 0; i < 8; i++)
        #pragma unroll
        for (int j = 0; j < 8; j++) acc[i][j] = 0.0f;

    const int nt = K >> 4;
    for (int t = 0; t < nt; t++) {
        const int cur = t & 1;
        if (t + 1 < nt) {
            const float* Ap2 = Ap + (t + 1) * 16;
            a0 = *(const float4*)Ap2;
            a1 = *(const float4*)(Ap2 + (size_t)64 * K);
            const float* Bp2 = Bp + (size_t)(t + 1) * 16 * N;
            b0 = *(const float4*)Bp2;
            b1 = *(const float4*)(Bp2 + (size_t)8 * N);
        }
        #pragma unroll
        for (int k = 0; k < 16; k++) {
            float4 xa0 = *(const float4*)&As[cur][k][ty << 2];
            float4 xa1 = *(const float4*)&As[cur][k][64 + (ty << 2)];
            float4 xb0 = *(const float4*)&Bs[cur][k][tx << 2];
            float4 xb1 = *(const float4*)&Bs[cur][k][64 + (tx << 2)];
            float ar[8] = {xa0.x, xa0.y, xa0.z, xa0.w, xa1.x, xa1.y, xa1.z, xa1.w};
            float br[8] = {xb0.x, xb0.y, xb0.z, xb0.w, xb1.x, xb1.y, xb1.z, xb1.w};
            #pragma unroll
            for (int i = 0; i < 8; i++)
                #pragma unroll
                for (int j = 0; j < 8; j++)
                    acc[i][j] = fmaf(ar[i], br[j], acc[i][j]);
        }
        if (t + 1 < nt) {
            const int nxt = cur ^ 1;
            As[nxt][aCol + 0][aRow]      = a0.x;
            As[nxt][aCol + 1][aRow]      = a0.y;
            As[nxt][aCol + 2][aRow]      = a0.z;
            As[nxt][aCol + 3][aRow]      = a0.w;
            As[nxt][aCol + 0][64 + aRow] = a1.x;
            As[nxt][aCol + 1][64 + aRow] = a1.y;
            As[nxt][aCol + 2][64 + aRow] = a1.z;
            As[nxt][aCol + 3][64 + aRow] = a1.w;
            *(float4*)&Bs[nxt][bRow][bCol]     = b0;
            *(float4*)&Bs[nxt][8 + bRow][bCol] = b1;
            __syncthreads();
        }
    }

    // Epilogue + store
    #pragma unroll
    for (int i = 0; i < 8; i++) {
        const int r = bm + ((i < 4) ? ((ty << 2) + i) : (64 + (ty << 2) + i - 4));
        const float mval = (float)mask[r];
        float* Crow = C + (size_t)r * N + bn;
        #pragma unroll
        for (int jh = 0; jh < 2; jh++) {
            const int cbase = jh * 64 + (tx << 2);
            float4 v;
            v.x = acc[i][jh * 4 + 0];
            v.y = acc[i][jh * 4 + 1];
            v.z = acc[i][jh * 4 + 2];
            v.w = acc[i][jh * 4 + 3];
            if (EPI == 0) {
                const int cglob = bn + cbase;   // all 4 cols in same segment
                if (cglob < DMODEL) {
                    v.x = phi_f(v.x); v.y = phi_f(v.y);
                    v.z = phi_f(v.z); v.w = phi_f(v.w);
                } else if (cglob < 2 * DMODEL) {
                    v.x = phi_f(v.x) * mval; v.y = phi_f(v.y) * mval;
                    v.z = phi_f(v.z) * mval; v.w = phi_f(v.w) * mval;
                } else {
                    v.x *= mval; v.y *= mval; v.z *= mval; v.w *= mval;
                }
            } else {
                v.x *= mval; v.y *= mval; v.z *= mval; v.w *= mval;
            }
            *(float4*)(Crow + cbase) = v;
        }
    }
}

// ------------------------------------------------------------------
// kv partials: per (b,h,chunk): kv[d][m] += k[l][d]*v[l][m], ksum[d] += k[l][d]
// over 1024 rows per chunk. 256 threads; thread owns 4x4 of the 64x64 output.
// ------------------------------------------------------------------
__global__ __launch_bounds__(256)
void kv_partial_kernel(const float* __restrict__ qkv)
{
    const int bh    = blockIdx.x;   // 0..63
    const int chunk = blockIdx.y;   // 0..7
    const int b = bh >> 4, h = bh & 15;
    const int tid = threadIdx.x;
    const int tdg = tid >> 4;       // d block (0..15)
    const int tmg = tid & 15;       // m block (0..15)

    __shared__ float ks[32][64];
    __shared__ float vs[32][64];

    float acc[4][4] = {{0.f,0.f,0.f,0.f},{0.f,0.f,0.f,0.f},
                       {0.f,0.f,0.f,0.f},{0.f,0.f,0.f,0.f}};
    float ksacc[4] = {0.f, 0.f, 0.f, 0.f};

    const size_t rowbase = (size_t)b * L_SEQ + (size_t)chunk * 1024;
    const int kcol = DMODEL + h * DH;
    const int vcol = 2 * DMODEL + h * DH;

    const int lrow = tid >> 4;          // 0..15 (+16 for second half)
    const int lcol = (tid & 15) << 2;   // 0..60

    for (int l0 = 0; l0 < 1024; l0 += 32) {
        const float* kp = qkv + (rowbase + l0 + lrow) * NQKV + kcol + lcol;
        const float* vp = qkv + (rowbase + l0 + lrow) * NQKV + vcol + lcol;
        float4 k0 = *(const float4*)kp;
        float4 k1 = *(const float4*)(kp + 16 * NQKV);
        float4 v0 = *(const float4*)vp;
        float4 v1 = *(const float4*)(vp + 16 * NQKV);
        __syncthreads();
        *(float4*)&ks[lrow][lcol]      = k0;
        *(float4*)&ks[16 + lrow][lcol] = k1;
        *(float4*)&vs[lrow][lcol]      = v0;
        *(float4*)&vs[16 + lrow][lcol] = v1;
        __syncthreads();
        #pragma unroll
        for (int l = 0; l < 32; l++) {
            float4 kd = *(const float4*)&ks[l][tdg << 2];
            float4 vm = *(const float4*)&vs[l][tmg << 2];
            float kr[4] = {kd.x, kd.y, kd.z, kd.w};
            float vr[4] = {vm.x, vm.y, vm.z, vm.w};
            #pragma unroll
            for (int i = 0; i < 4; i++)
                #pragma unroll
                for (int j = 0; j < 4; j++)
                    acc[i][j] = fmaf(kr[i], vr[j], acc[i][j]);
            if (tmg == 0) {
                #pragma unroll
                for (int i = 0; i < 4; i++) ksacc[i] += kr[i];
            }
        }
    }

    #pragma unroll
    for (int i = 0; i < 4; i++) {
        const int d = (tdg << 2) + i;
        #pragma unroll
        for (int j = 0; j < 4; j++)
            g_kv_part[chunk][bh][d][(tmg << 2) + j] = acc[i][j];
        if (tmg == 0) g_ksum_part[chunk][bh][d] = ksacc[i];
    }
}

// Reduce NCHUNK partials -> g_kv, g_ksum
__global__ void kv_reduce_kernel()
{
    const int NKV = BATCH * NHEADS * DH * DH;   // 262144
    const int NKS = BATCH * NHEADS * DH;        // 4096
    const int idx = blockIdx.x * blockDim.x + threadIdx.x;
    if (idx < NKV) {
        const float* p = &g_kv_part[0][0][0][0];
        float s = 0.f;
        #pragma unroll
        for (int c = 0; c < NCHUNK; c++) s += p[(size_t)c * NKV + idx];
        (&g_kv[0][0][0])[idx] = s;
    } else if (idx < NKV + NKS) {
        const int e = idx - NKV;
        const float* p = &g_ksum_part[0][0][0];
        float s = 0.f;
        #pragma unroll
        for (int c = 0; c < NCHUNK; c++) s += p[(size_t)c * NKS + e];
        (&g_ksum[0][0])[e] = s;
    }
}

// ------------------------------------------------------------------
// y[l, h*64+m] = (1/(q·ksum + eps)) * sum_d q[l,d] * kv[d][m]
// Block = (b,h, 128-row tile); 128 threads, one row each; kv staged in smem.
// ------------------------------------------------------------------
__global__ __launch_bounds__(128)
void apply_kv_kernel(const float* __restrict__ qkv, float* __restrict__ y)
{
    const int bh = blockIdx.x;   // 0..63
    const int lt = blockIdx.y;   // 0..63
    const int b = bh >> 4, h = bh & 15;
    const int tid = threadIdx.x;

    __shared__ float kvs[DH][DH];
    __shared__ float kss[DH];

    const float* kvg = &g_kv[bh][0][0];
    #pragma unroll
    for (int i = 0; i < 8; i++) {
        const int f = tid + i * 128;                 // float4 index 0..1023
        ((float4*)&kvs[0][0])[f] = ((const float4*)kvg)[f];
    }
    if (tid < 16)
        ((float4*)&kss[0])[tid] = ((const float4*)&g_ksum[bh][0])[tid];
    __syncthreads();

    const size_t row = (size_t)b * L_SEQ + (size_t)lt * 128 + tid;
    const float* qp = qkv + row * NQKV + h * DH;

    float q[64];
    #pragma unroll
    for (int i = 0; i < 16; i++) {
        float4 t4 = *(const float4*)(qp + i * 4);
        q[4 * i + 0] = t4.x; q[4 * i + 1] = t4.y;
        q[4 * i + 2] = t4.z; q[4 * i + 3] = t4.w;
    }

    float den = EPSV;
    #pragma unroll
    for (int d = 0; d < 64; d++) den = fmaf(q[d], kss[d], den);
    const float z = 1.0f / den;

    float* yp = y + row * DMODEL + h * DH;
    #pragma unroll
    for (int mc = 0; mc < 4; mc++) {
        float acc[16];
        #pragma unroll
        for (int j = 0; j < 16; j++) acc[j] = 0.f;
        #pragma unroll
        for (int d = 0; d < 64; d++) {
            const float qd = q[d];
            #pragma unroll
            for (int j4 = 0; j4 < 4; j4++) {
                float4 kvv = *(const float4*)&kvs[d][mc * 16 + j4 * 4];
                acc[j4 * 4 + 0] = fmaf(qd, kvv.x, acc[j4 * 4 + 0]);
                acc[j4 * 4 + 1] = fmaf(qd, kvv.y, acc[j4 * 4 + 1]);
                acc[j4 * 4 + 2] = fmaf(qd, kvv.z, acc[j4 * 4 + 2]);
                acc[j4 * 4 + 3] = fmaf(qd, kvv.w, acc[j4 * 4 + 3]);
            }
        }
        #pragma unroll
        for (int j4 = 0; j4 < 4; j4++) {
            float4 o;
            o.x = acc[j4 * 4 + 0] * z;
            o.y = acc[j4 * 4 + 1] * z;
            o.z = acc[j4 * 4 + 2] * z;
            o.w = acc[j4 * 4 + 3] * z;
            *(float4*)(yp + mc * 16 + j4 * 4) = o;
        }
    }
}

// ------------------------------------------------------------------
extern "C" void kernel_launch(void* const* d_in, const int* in_sizes, int n_in,
                              void* d_out, int out_size)
{
    const float* x    = (const float*)d_in[0];
    const int*   mask = (const int*)d_in[1];
    const float* Wqkv = (const float*)d_in[2];
    const float* Wout = (const float*)d_in[3];
    float* out = (float*)d_out;

    float* qkv = nullptr;
    float* y   = nullptr;
    cudaGetSymbolAddress((void**)&qkv, g_qkv);
    cudaGetSymbolAddress((void**)&y,   g_y);

    // 1) qkv GEMM with phi/mask epilogue
    sgemm_kernel<0><<<dim3(NQKV / 128, MROWS / 128), 256>>>(
        x, Wqkv, qkv, MROWS, NQKV, DMODEL, mask);

    // 2) kv / ksum split-L partials + reduce
    kv_partial_kernel<<<dim3(BATCH * NHEADS, NCHUNK), 256>>>(qkv);
    {
        const int total = BATCH * NHEADS * DH * DH + BATCH * NHEADS * DH;
        kv_reduce_kernel<<<(total + 255) / 256, 256>>>();
    }

    // 3) y = (q @ kv) * z
    apply_kv_kernel<<<dim3(BATCH * NHEADS, L_SEQ / 128), 128>>>(qkv, y);

    // 4) out = (y @ Wout) * mask
    sgemm_kernel<1><<<dim3(DMODEL / 128, MROWS / 128), 256>>>(
        y, Wout, out, MROWS, DMODEL, DMODEL, mask);
}

// round 2
// speedup vs baseline: 1.0011x; 1.0011x over previous
#include <cuda_runtime.h>
#include <math.h>

// Problem constants (fixed shapes from reference)
#define L_SEQ   8192
#define BATCH   4
#define DMODEL  1024
#define NHEADS  16
#define DH      64
#define MROWS   (BATCH * L_SEQ)      // 32768
#define NQKV    (3 * DMODEL)         // 3072
#define EPSV    1e-6f
#define NCHUNK  8                    // L-split chunks for kv reduction

// ------------------------------------------------------------------
// Scratch (device globals; no allocation allowed in kernel_launch)
// ------------------------------------------------------------------
__device__ float g_qkv[(size_t)MROWS * NQKV];            // phi(q) | phi(k)*m | v*m
__device__ float g_y[(size_t)MROWS * DMODEL];            // attention output pre-Wout
__device__ float g_kv_part[NCHUNK][BATCH * NHEADS][DH][DH];
__device__ float g_ksum_part[NCHUNK][BATCH * NHEADS][DH];
__device__ float g_kv[BATCH * NHEADS][DH][DH];
__device__ float g_ksum[BATCH * NHEADS][DH];

__device__ __forceinline__ float phi_f(float z) {
    // elu(z)+1 : z>0 ? z+1 : exp(z)
    return z > 0.0f ? z + 1.0f : __expf(z);
}

// ------------------------------------------------------------------
// SGEMM: C[M,N] = A[M,K] @ B[K,N], row-major, M%128==0, N%128==0, K%16==0
// EPI 0: qkv epilogue  (cols [0,1024): phi ; [1024,2048): phi*mask ; [2048,3072): *mask)
// EPI 1: out epilogue  (*mask[row])
// 128x128 tile, 256 threads, 8x8 per thread, BK=16, double-buffered smem.
// ------------------------------------------------------------------
template <int EPI>
__global__ __launch_bounds__(256)
void sgemm_kernel(const float* __restrict__ A, const float* __restrict__ B,
                  float* __restrict__ C, int M, int N, int K,
                  const int* __restrict__ mask)
{
    __shared__ float As[2][16][128];
    __shared__ float Bs[2][16][128];

    const int tid = threadIdx.x;
    const int tx  = tid & 15;          // N-dim thread coord (0..15)
    const int ty  = tid >> 4;          // M-dim thread coord (0..15)
    const int bm  = blockIdx.y * 128;
    const int bn  = blockIdx.x * 128;

    // A tile: 128 rows x 16 cols = 512 float4; thread loads f=tid and f=tid+256
    const int aRow = tid >> 2;            // 0..63 (+64 for second)
    const int aCol = (tid & 3) << 2;      // 0,4,8,12
    // B tile: 16 rows x 128 cols = 512 float4
    const int bRow = tid >> 5;            // 0..7 (+8 for second)
    const int bCol = (tid & 31) << 2;     // 0..124

    const float* Ap = A + (size_t)(bm + aRow) * K + aCol;
    const float* Bp = B + (size_t)bRow * N + bn + bCol;

    float4 a0 = *(const float4*)Ap;
    float4 a1 = *(const float4*)(Ap + (size_t)64 * K);
    float4 b0 = *(const float4*)Bp;
    float4 b1 = *(const float4*)(Bp + (size_t)8 * N);

    // store tile 0 (A transposed into [k][m])
    As[0][aCol + 0][aRow]      = a0.x;
    As[0][aCol + 1][aRow]      = a0.y;
    As[0][aCol + 2][aRow]      = a0.z;
    As[0][aCol + 3][aRow]      = a0.w;
    As[0][aCol + 0][64 + aRow] = a1.x;
    As[0][aCol + 1][64 + aRow] = a1.y;
    As[0][aCol + 2][64 + aRow] = a1.z;
    As[0][aCol + 3][64 + aRow] = a1.w;
    *(float4*)&Bs[0][bRow][bCol]     = b0;
    *(float4*)&Bs[0][8 + bRow][bCol] = b1;
    __syncthreads();

    float acc[8][8];
    #pragma unroll
    for (int i = 0; i < 8; i++)
        #pragma unroll
        for (int j = 0; j < 8; j++) acc[i][j] = 0.0f;

    const int nt = K >> 4;
    for (int t = 0; t < nt; t++) {
        const int cur = t & 1;
        if (t + 1 < nt) {
            const float* Ap2 = Ap + (t + 1) * 16;
            a0 = *(const float4*)Ap2;
            a1 = *(const float4*)(Ap2 + (size_t)64 * K);
            const float* Bp2 = Bp + (size_t)(t + 1) * 16 * N;
            b0 = *(const float4*)Bp2;
            b1 = *(const float4*)(Bp2 + (size_t)8 * N);
        }
        #pragma unroll
        for (int k = 0; k < 16; k++) {
            float4 xa0 = *(const float4*)&As[cur][k][ty << 2];
            float4 xa1 = *(const float4*)&As[cur][k][64 + (ty << 2)];
            float4 xb0 = *(const float4*)&Bs[cur][k][tx << 2];
            float4 xb1 = *(const float4*)&Bs[cur][k][64 + (tx << 2)];
            float ar[8] = {xa0.x, xa0.y, xa0.z, xa0.w, xa1.x, xa1.y, xa1.z, xa1.w};
            float br[8] = {xb0.x, xb0.y, xb0.z, xb0.w, xb1.x, xb1.y, xb1.z, xb1.w};
            #pragma unroll
            for (int i = 0; i < 8; i++)
                #pragma unroll
                for (int j = 0; j < 8; j++)
                    acc[i][j] = fmaf(ar[i], br[j], acc[i][j]);
        }
        if (t + 1 < nt) {
            const int nxt = cur ^ 1;
            As[nxt][aCol + 0][aRow]      = a0.x;
            As[nxt][aCol + 1][aRow]      = a0.y;
            As[nxt][aCol + 2][aRow]      = a0.z;
            As[nxt][aCol + 3][aRow]      = a0.w;
            As[nxt][aCol + 0][64 + aRow] = a1.x;
            As[nxt][aCol + 1][64 + aRow] = a1.y;
            As[nxt][aCol + 2][64 + aRow] = a1.z;
            As[nxt][aCol + 3][64 + aRow] = a1.w;
            *(float4*)&Bs[nxt][bRow][bCol]     = b0;
            *(float4*)&Bs[nxt][8 + bRow][bCol] = b1;
            __syncthreads();
        }
    }

    // Epilogue + store
    #pragma unroll
    for (int i = 0; i < 8; i++) {
        const int r = bm + ((i < 4) ? ((ty << 2) + i) : (64 + (ty << 2) + i - 4));
        const float mval = (float)mask[r];
        float* Crow = C + (size_t)r * N + bn;
        #pragma unroll
        for (int jh = 0; jh < 2; jh++) {
            const int cbase = jh * 64 + (tx << 2);
            float4 v;
            v.x = acc[i][jh * 4 + 0];
            v.y = acc[i][jh * 4 + 1];
            v.z = acc[i][jh * 4 + 2];
            v.w = acc[i][jh * 4 + 3];
            if (EPI == 0) {
                const int cglob = bn + cbase;   // all 4 cols in same segment
                if (cglob < DMODEL) {
                    v.x = phi_f(v.x); v.y = phi_f(v.y);
                    v.z = phi_f(v.z); v.w = phi_f(v.w);
                } else if (cglob < 2 * DMODEL) {
                    v.x = phi_f(v.x) * mval; v.y = phi_f(v.y) * mval;
                    v.z = phi_f(v.z) * mval; v.w = phi_f(v.w) * mval;
                } else {
                    v.x *= mval; v.y *= mval; v.z *= mval; v.w *= mval;
                }
            } else {
                v.x *= mval; v.y *= mval; v.z *= mval; v.w *= mval;
            }
            *(float4*)(Crow + cbase) = v;
        }
    }
}

// ------------------------------------------------------------------
// kv partials: per (b,h,chunk): kv[d][m] += k[l][d]*v[l][m], ksum[d] += k[l][d]
// over 1024 rows per chunk. 256 threads; thread owns 4x4 of the 64x64 output.
// ------------------------------------------------------------------
__global__ __launch_bounds__(256)
void kv_partial_kernel(const float* __restrict__ qkv)
{
    const int bh    = blockIdx.x;   // 0..63
    const int chunk = blockIdx.y;   // 0..7
    const int b = bh >> 4, h = bh & 15;
    const int tid = threadIdx.x;
    const int tdg = tid >> 4;       // d block (0..15)
    const int tmg = tid & 15;       // m block (0..15)

    __shared__ float ks[32][64];
    __shared__ float vs[32][64];

    float acc[4][4] = {{0.f,0.f,0.f,0.f},{0.f,0.f,0.f,0.f},
                       {0.f,0.f,0.f,0.f},{0.f,0.f,0.f,0.f}};
    float ksacc[4] = {0.f, 0.f, 0.f, 0.f};

    const size_t rowbase = (size_t)b * L_SEQ + (size_t)chunk * 1024;
    const int kcol = DMODEL + h * DH;
    const int vcol = 2 * DMODEL + h * DH;

    const int lrow = tid >> 4;          // 0..15 (+16 for second half)
    const int lcol = (tid & 15) << 2;   // 0..60

    for (int l0 = 0; l0 < 1024; l0 += 32) {
        const float* kp = qkv + (rowbase + l0 + lrow) * NQKV + kcol + lcol;
        const float* vp = qkv + (rowbase + l0 + lrow) * NQKV + vcol + lcol;
        float4 k0 = *(const float4*)kp;
        float4 k1 = *(const float4*)(kp + 16 * NQKV);
        float4 v0 = *(const float4*)vp;
        float4 v1 = *(const float4*)(vp + 16 * NQKV);
        __syncthreads();
        *(float4*)&ks[lrow][lcol]      = k0;
        *(float4*)&ks[16 + lrow][lcol] = k1;
        *(float4*)&vs[lrow][lcol]      = v0;
        *(float4*)&vs[16 + lrow][lcol] = v1;
        __syncthreads();
        #pragma unroll
        for (int l = 0; l < 32; l++) {
            float4 kd = *(const float4*)&ks[l][tdg << 2];
            float4 vm = *(const float4*)&vs[l][tmg << 2];
            float kr[4] = {kd.x, kd.y, kd.z, kd.w};
            float vr[4] = {vm.x, vm.y, vm.z, vm.w};
            #pragma unroll
            for (int i = 0; i < 4; i++)
                #pragma unroll
                for (int j = 0; j < 4; j++)
                    acc[i][j] = fmaf(kr[i], vr[j], acc[i][j]);
            if (tmg == 0) {
                #pragma unroll
                for (int i = 0; i < 4; i++) ksacc[i] += kr[i];
            }
        }
    }

    #pragma unroll
    for (int i = 0; i < 4; i++) {
        const int d = (tdg << 2) + i;
        #pragma unroll
        for (int j = 0; j < 4; j++)
            g_kv_part[chunk][bh][d][(tmg << 2) + j] = acc[i][j];
        if (tmg == 0) g_ksum_part[chunk][bh][d] = ksacc[i];
    }
}

// Reduce NCHUNK partials -> g_kv, g_ksum
__global__ void kv_reduce_kernel()
{
    const int NKV = BATCH * NHEADS * DH * DH;   // 262144
    const int NKS = BATCH * NHEADS * DH;        // 4096
    const int idx = blockIdx.x * blockDim.x + threadIdx.x;
    if (idx < NKV) {
        const float* p = &g_kv_part[0][0][0][0];
        float s = 0.f;
        #pragma unroll
        for (int c = 0; c < NCHUNK; c++) s += p[(size_t)c * NKV + idx];
        (&g_kv[0][0][0])[idx] = s;
    } else if (idx < NKV + NKS) {
        const int e = idx - NKV;
        const float* p = &g_ksum_part[0][0][0];
        float s = 0.f;
        #pragma unroll
        for (int c = 0; c < NCHUNK; c++) s += p[(size_t)c * NKS + e];
        (&g_ksum[0][0])[e] = s;
    }
}

// ------------------------------------------------------------------
// y[l, h*64+m] = (1/(q·ksum + eps)) * sum_d q[l,d] * kv[d][m]
// Block = (b,h, 128-row tile); 128 threads, one row each; kv staged in smem.
// ------------------------------------------------------------------
__global__ __launch_bounds__(128)
void apply_kv_kernel(const float* __restrict__ qkv, float* __restrict__ y)
{
    const int bh = blockIdx.x;   // 0..63
    const int lt = blockIdx.y;   // 0..63
    const int b = bh >> 4, h = bh & 15;
    const int tid = threadIdx.x;

    __shared__ float kvs[DH][DH];
    __shared__ float kss[DH];

    const float* kvg = &g_kv[bh][0][0];
    #pragma unroll
    for (int i = 0; i < 8; i++) {
        const int f = tid + i * 128;                 // float4 index 0..1023
        ((float4*)&kvs[0][0])[f] = ((const float4*)kvg)[f];
    }
    if (tid < 16)
        ((float4*)&kss[0])[tid] = ((const float4*)&g_ksum[bh][0])[tid];
    __syncthreads();

    const size_t row = (size_t)b * L_SEQ + (size_t)lt * 128 + tid;
    const float* qp = qkv + row * NQKV + h * DH;

    float q[64];
    #pragma unroll
    for (int i = 0; i < 16; i++) {
        float4 t4 = *(const float4*)(qp + i * 4);
        q[4 * i + 0] = t4.x; q[4 * i + 1] = t4.y;
        q[4 * i + 2] = t4.z; q[4 * i + 3] = t4.w;
    }

    float den = EPSV;
    #pragma unroll
    for (int d = 0; d < 64; d++) den = fmaf(q[d], kss[d], den);
    const float z = 1.0f / den;

    float* yp = y + row * DMODEL + h * DH;
    #pragma unroll
    for (int mc = 0; mc < 4; mc++) {
        float acc[16];
        #pragma unroll
        for (int j = 0; j < 16; j++) acc[j] = 0.f;
        #pragma unroll
        for (int d = 0; d < 64; d++) {
            const float qd = q[d];
            #pragma unroll
            for (int j4 = 0; j4 < 4; j4++) {
                float4 kvv = *(const float4*)&kvs[d][mc * 16 + j4 * 4];
                acc[j4 * 4 + 0] = fmaf(qd, kvv.x, acc[j4 * 4 + 0]);
                acc[j4 * 4 + 1] = fmaf(qd, kvv.y, acc[j4 * 4 + 1]);
                acc[j4 * 4 + 2] = fmaf(qd, kvv.z, acc[j4 * 4 + 2]);
                acc[j4 * 4 + 3] = fmaf(qd, kvv.w, acc[j4 * 4 + 3]);
            }
        }
        #pragma unroll
        for (int j4 = 0; j4 < 4; j4++) {
            float4 o;
            o.x = acc[j4 * 4 + 0] * z;
            o.y = acc[j4 * 4 + 1] * z;
            o.z = acc[j4 * 4 + 2] * z;
            o.w = acc[j4 * 4 + 3] * z;
            *(float4*)(yp + mc * 16 + j4 * 4) = o;
        }
    }
}

// ------------------------------------------------------------------
extern "C" void kernel_launch(void* const* d_in, const int* in_sizes, int n_in,
                              void* d_out, int out_size)
{
    const float* x    = (const float*)d_in[0];
    const int*   mask = (const int*)d_in[1];
    const float* Wqkv = (const float*)d_in[2];
    const float* Wout = (const float*)d_in[3];
    float* out = (float*)d_out;

    float* qkv = nullptr;
    float* y   = nullptr;
    cudaGetSymbolAddress((void**)&qkv, g_qkv);
    cudaGetSymbolAddress((void**)&y,   g_y);

    // 1) qkv GEMM with phi/mask epilogue
    sgemm_kernel<0><<<dim3(NQKV / 128, MROWS / 128), 256>>>(
        x, Wqkv, qkv, MROWS, NQKV, DMODEL, mask);

    // 2) kv / ksum split-L partials + reduce
    kv_partial_kernel<<<dim3(BATCH * NHEADS, NCHUNK), 256>>>(qkv);
    {
        const int total = BATCH * NHEADS * DH * DH + BATCH * NHEADS * DH;
        kv_reduce_kernel<<<(total + 255) / 256, 256>>>();
    }

    // 3) y = (q @ kv) * z
    apply_kv_kernel<<<dim3(BATCH * NHEADS, L_SEQ / 128), 128>>>(qkv, y);

    // 4) out = (y @ Wout) * mask
    sgemm_kernel<1><<<dim3(DMODEL / 128, MROWS / 128), 256>>>(
        y, Wout, out, MROWS, DMODEL, DMODEL, mask);
}

// round 6
// speedup vs baseline: 1.2777x; 1.2762x over previous
#include <cuda_runtime.h>
#include <math.h>
#include <stdint.h>

// Problem constants (fixed shapes from reference)
#define L_SEQ   8192
#define BATCH   4
#define DMODEL  1024
#define NHEADS  16
#define DH      64
#define MROWS   (BATCH * L_SEQ)      // 32768
#define NQKV    (3 * DMODEL)         // 3072
#define EPSV    1e-6f
#define NCHUNK  8                    // L-split chunks for kv reduction

// ------------------------------------------------------------------
// Scratch (device globals; no allocation allowed in kernel_launch)
// ------------------------------------------------------------------
__device__ float g_qkv[(size_t)MROWS * NQKV];            // phi(q) | phi(k)*m | v*m
__device__ float g_y[(size_t)MROWS * DMODEL];            // attention output pre-Wout
__device__ float g_kv_part[NCHUNK][BATCH * NHEADS][DH][DH];
__device__ float g_ksum_part[NCHUNK][BATCH * NHEADS][DH];
__device__ float g_kv[BATCH * NHEADS][DH][DH];
__device__ float g_ksum[BATCH * NHEADS][DH];

__device__ __forceinline__ float phi_f(float z) {
    return z > 0.0f ? z + 1.0f : __expf(z);
}

// Round-to-nearest tf32 conversion (unbiased; truncation would bias ~1e-3 over K=1024)
__device__ __forceinline__ unsigned f2tf(float f) {
    unsigned u;
    asm("cvt.rna.tf32.f32 %0, %1;" : "=r"(u) : "f"(f));
    return u;
}

__device__ __forceinline__ void mma_tf32(float* c, const unsigned* a, const unsigned* b) {
    asm volatile(
        "mma.sync.aligned.m16n8k8.row.col.f32.tf32.tf32.f32 "
        "{%0,%1,%2,%3}, {%4,%5,%6,%7}, {%8,%9}, {%0,%1,%2,%3};"
        : "+f"(c[0]), "+f"(c[1]), "+f"(c[2]), "+f"(c[3])
        : "r"(a[0]), "r"(a[1]), "r"(a[2]), "r"(a[3]), "r"(b[0]), "r"(b[1]));
}

// ------------------------------------------------------------------
// TF32 tensor-core GEMM: C[M,N] = A[M,K] @ B[K,N] (row-major)
// Block 128x128, BK=16, 256 threads = 8 warps (2 x 4), warp tile 64x32.
// Each warp: 4 m-tiles (16) x 4 n-tiles (8), mma m16n8k8, fp32 accum.
// EPI 0: qkv epilogue (col segment 0: phi ; 1: phi*mask ; 2: *mask)
// EPI 1: out epilogue (*mask[row])
// ------------------------------------------------------------------
template <int EPI>
__global__ __launch_bounds__(256, 2)
void tgemm_kernel(const float* __restrict__ A, const float* __restrict__ B,
                  float* __restrict__ C, int M, int N, int K,
                  const int* __restrict__ mask)
{
    __shared__ unsigned As[2][16][128];   // A transposed: [k][m], tf32 bits
    __shared__ unsigned Bs[2][16][128];   // [k][n], tf32 bits

    const int tid  = threadIdx.x;
    const int warp = tid >> 5;
    const int lane = tid & 31;
    const int wm   = warp >> 2;      // 0..1
    const int wn   = warp & 3;       // 0..3
    const int lr   = lane >> 2;      // 0..7
    const int lc   = lane & 3;       // 0..3

    const int bm = blockIdx.y * 128;
    const int bn = blockIdx.x * 128;

    const int aRow = tid >> 2;            // 0..63 (+64)
    const int aCol = (tid & 3) << 2;      // 0,4,8,12
    const int bRow = tid >> 5;            // 0..7 (+8)
    const int bCol = (tid & 31) << 2;     // 0..124

    const float* Ap = A + (size_t)(bm + aRow) * K + aCol;
    const float* Bp = B + (size_t)bRow * N + bn + bCol;

    float4 a0 = *(const float4*)Ap;
    float4 a1 = *(const float4*)(Ap + (size_t)64 * K);
    float4 b0 = *(const float4*)Bp;
    float4 b1 = *(const float4*)(Bp + (size_t)8 * N);

    // stage tile 0
    As[0][aCol + 0][aRow]      = f2tf(a0.x);
    As[0][aCol + 1][aRow]      = f2tf(a0.y);
    As[0][aCol + 2][aRow]      = f2tf(a0.z);
    As[0][aCol + 3][aRow]      = f2tf(a0.w);
    As[0][aCol + 0][64 + aRow] = f2tf(a1.x);
    As[0][aCol + 1][64 + aRow] = f2tf(a1.y);
    As[0][aCol + 2][64 + aRow] = f2tf(a1.z);
    As[0][aCol + 3][64 + aRow] = f2tf(a1.w);
    {
        uint4 c0 = make_uint4(f2tf(b0.x), f2tf(b0.y), f2tf(b0.z), f2tf(b0.w));
        uint4 c1 = make_uint4(f2tf(b1.x), f2tf(b1.y), f2tf(b1.z), f2tf(b1.w));
        *(uint4*)&Bs[0][bRow][bCol]     = c0;
        *(uint4*)&Bs[0][8 + bRow][bCol] = c1;
    }
    __syncthreads();

    float acc[4][4][4];
    #pragma unroll
    for (int mt = 0; mt < 4; mt++)
        #pragma unroll
        for (int nt = 0; nt < 4; nt++)
            #pragma unroll
            for (int e = 0; e < 4; e++) acc[mt][nt][e] = 0.0f;

    const int nt_tiles = K >> 4;
    for (int t = 0; t < nt_tiles; t++) {
        const int cur = t & 1;
        if (t + 1 < nt_tiles) {
            const float* Ap2 = Ap + (t + 1) * 16;
            a0 = *(const float4*)Ap2;
            a1 = *(const float4*)(Ap2 + (size_t)64 * K);
            const float* Bp2 = Bp + (size_t)(t + 1) * 16 * N;
            b0 = *(const float4*)Bp2;
            b1 = *(const float4*)(Bp2 + (size_t)8 * N);
        }

        #pragma unroll
        for (int ks = 0; ks < 2; ks++) {
            unsigned af[4][4];
            unsigned bf[4][2];
            #pragma unroll
            for (int mt = 0; mt < 4; mt++) {
                const int m0 = wm * 64 + mt * 16 + lr;
                af[mt][0] = As[cur][ks * 8 + lc][m0];
                af[mt][1] = As[cur][ks * 8 + lc][m0 + 8];
                af[mt][2] = As[cur][ks * 8 + lc + 4][m0];
                af[mt][3] = As[cur][ks * 8 + lc + 4][m0 + 8];
            }
            #pragma unroll
            for (int nt = 0; nt < 4; nt++) {
                const int n0 = wn * 32 + nt * 8 + lr;
                bf[nt][0] = Bs[cur][ks * 8 + lc][n0];
                bf[nt][1] = Bs[cur][ks * 8 + lc + 4][n0];
            }
            #pragma unroll
            for (int mt = 0; mt < 4; mt++)
                #pragma unroll
                for (int nt = 0; nt < 4; nt++)
                    mma_tf32(acc[mt][nt], af[mt], bf[nt]);
        }

        if (t + 1 < nt_tiles) {
            const int nxt = cur ^ 1;
            As[nxt][aCol + 0][aRow]      = f2tf(a0.x);
            As[nxt][aCol + 1][aRow]      = f2tf(a0.y);
            As[nxt][aCol + 2][aRow]      = f2tf(a0.z);
            As[nxt][aCol + 3][aRow]      = f2tf(a0.w);
            As[nxt][aCol + 0][64 + aRow] = f2tf(a1.x);
            As[nxt][aCol + 1][64 + aRow] = f2tf(a1.y);
            As[nxt][aCol + 2][64 + aRow] = f2tf(a1.z);
            As[nxt][aCol + 3][64 + aRow] = f2tf(a1.w);
            uint4 c0 = make_uint4(f2tf(b0.x), f2tf(b0.y), f2tf(b0.z), f2tf(b0.w));
            uint4 c1 = make_uint4(f2tf(b1.x), f2tf(b1.y), f2tf(b1.z), f2tf(b1.w));
            *(uint4*)&Bs[nxt][bRow][bCol]     = c0;
            *(uint4*)&Bs[nxt][8 + bRow][bCol] = c1;
            __syncthreads();
        }
    }

    // Epilogue: block columns [bn, bn+128) lie in one 1024-segment (128 | 1024)
    const int seg = bn >> 10;   // EPI 0: 0=phi, 1=phi*mask, 2=*mask
    #pragma unroll
    for (int mt = 0; mt < 4; mt++) {
        const int r0 = bm + wm * 64 + mt * 16 + lr;
        const float mv0 = (float)mask[r0];
        const float mv1 = (float)mask[r0 + 8];
        #pragma unroll
        for (int nt = 0; nt < 4; nt++) {
            const int c = bn + wn * 32 + nt * 8 + lc * 2;
            float2 v0 = make_float2(acc[mt][nt][0], acc[mt][nt][1]);
            float2 v1 = make_float2(acc[mt][nt][2], acc[mt][nt][3]);
            if (EPI == 0) {
                if (seg == 0) {
                    v0.x = phi_f(v0.x); v0.y = phi_f(v0.y);
                    v1.x = phi_f(v1.x); v1.y = phi_f(v1.y);
                } else if (seg == 1) {
                    v0.x = phi_f(v0.x) * mv0; v0.y = phi_f(v0.y) * mv0;
                    v1.x = phi_f(v1.x) * mv1; v1.y = phi_f(v1.y) * mv1;
                } else {
                    v0.x *= mv0; v0.y *= mv0;
                    v1.x *= mv1; v1.y *= mv1;
                }
            } else {
                v0.x *= mv0; v0.y *= mv0;
                v1.x *= mv1; v1.y *= mv1;
            }
            *(float2*)(C + (size_t)r0 * N + c)       = v0;
            *(float2*)(C + (size_t)(r0 + 8) * N + c) = v1;
        }
    }
}

// ------------------------------------------------------------------
// kv partials: per (b,h,chunk): kv[d][m] += k[l][d]*v[l][m], ksum[d] += k[l][d]
// ------------------------------------------------------------------
__global__ __launch_bounds__(256)
void kv_partial_kernel(const float* __restrict__ qkv)
{
    const int bh    = blockIdx.x;   // 0..63
    const int chunk = blockIdx.y;   // 0..7
    const int b = bh >> 4, h = bh & 15;
    const int tid = threadIdx.x;
    const int tdg = tid >> 4;       // d block (0..15)
    const int tmg = tid & 15;       // m block (0..15)

    __shared__ float ks[32][64];
    __shared__ float vs[32][64];

    float acc[4][4] = {{0.f,0.f,0.f,0.f},{0.f,0.f,0.f,0.f},
                       {0.f,0.f,0.f,0.f},{0.f,0.f,0.f,0.f}};
    float ksacc[4] = {0.f, 0.f, 0.f, 0.f};

    const size_t rowbase = (size_t)b * L_SEQ + (size_t)chunk * 1024;
    const int kcol = DMODEL + h * DH;
    const int vcol = 2 * DMODEL + h * DH;

    const int lrow = tid >> 4;          // 0..15 (+16)
    const int lcol = (tid & 15) << 2;   // 0..60

    for (int l0 = 0; l0 < 1024; l0 += 32) {
        const float* kp = qkv + (rowbase + l0 + lrow) * NQKV + kcol + lcol;
        const float* vp = qkv + (rowbase + l0 + lrow) * NQKV + vcol + lcol;
        float4 k0 = *(const float4*)kp;
        float4 k1 = *(const float4*)(kp + 16 * NQKV);
        float4 v0 = *(const float4*)vp;
        float4 v1 = *(const float4*)(vp + 16 * NQKV);
        __syncthreads();
        *(float4*)&ks[lrow][lcol]      = k0;
        *(float4*)&ks[16 + lrow][lcol] = k1;
        *(float4*)&vs[lrow][lcol]      = v0;
        *(float4*)&vs[16 + lrow][lcol] = v1;
        __syncthreads();
        #pragma unroll
        for (int l = 0; l < 32; l++) {
            float4 kd = *(const float4*)&ks[l][tdg << 2];
            float4 vm = *(const float4*)&vs[l][tmg << 2];
            float kr[4] = {kd.x, kd.y, kd.z, kd.w};
            float vr[4] = {vm.x, vm.y, vm.z, vm.w};
            #pragma unroll
            for (int i = 0; i < 4; i++)
                #pragma unroll
                for (int j = 0; j < 4; j++)
                    acc[i][j] = fmaf(kr[i], vr[j], acc[i][j]);
            if (tmg == 0) {
                #pragma unroll
                for (int i = 0; i < 4; i++) ksacc[i] += kr[i];
            }
        }
    }

    #pragma unroll
    for (int i = 0; i < 4; i++) {
        const int d = (tdg << 2) + i;
        #pragma unroll
        for (int j = 0; j < 4; j++)
            g_kv_part[chunk][bh][d][(tmg << 2) + j] = acc[i][j];
        if (tmg == 0) g_ksum_part[chunk][bh][d] = ksacc[i];
    }
}

__global__ void kv_reduce_kernel()
{
    const int NKV = BATCH * NHEADS * DH * DH;   // 262144
    const int NKS = BATCH * NHEADS * DH;        // 4096
    const int idx = blockIdx.x * blockDim.x + threadIdx.x;
    if (idx < NKV) {
        const float* p = &g_kv_part[0][0][0][0];
        float s = 0.f;
        #pragma unroll
        for (int c = 0; c < NCHUNK; c++) s += p[(size_t)c * NKV + idx];
        (&g_kv[0][0][0])[idx] = s;
    } else if (idx < NKV + NKS) {
        const int e = idx - NKV;
        const float* p = &g_ksum_part[0][0][0];
        float s = 0.f;
        #pragma unroll
        for (int c = 0; c < NCHUNK; c++) s += p[(size_t)c * NKS + e];
        (&g_ksum[0][0])[e] = s;
    }
}

// ------------------------------------------------------------------
// apply_kv v3: y[64 rows, 64] = (q @ kv) * z per (b,h, 64-row tile).
// 256 threads as 16x16 grid; thread tile 4 rows x 4 cols.
// smem: qs transposed 17.4KB + kvs 16.4KB + kss 0.25KB = 34KB (< 48KB).
// Denominator fused into main k-loop.
// ------------------------------------------------------------------
__global__ __launch_bounds__(256)
void apply_kv_kernel(const float* __restrict__ qkv, float* __restrict__ y)
{
    const int bh = blockIdx.x;   // 0..63
    const int lt = blockIdx.y;   // 0..127 (64-row tiles)
    const int b = bh >> 4, h = bh & 15;
    const int tid = threadIdx.x;
    const int tx = tid & 15;     // col group (4 cols)
    const int ty = tid >> 4;     // row group (4 rows)

    __shared__ float qs[DH][68];     // q transposed [d][row], padded
    __shared__ float kvs[DH][DH];
    __shared__ float kss[DH];

    const float* kvg = &g_kv[bh][0][0];
    #pragma unroll
    for (int i = 0; i < 4; i++) {
        const int f = tid + i * 256;
        ((float4*)&kvs[0][0])[f] = ((const float4*)kvg)[f];
    }
    if (tid < 16)
        ((float4*)&kss[0])[tid] = ((const float4*)&g_ksum[bh][0])[tid];

    const size_t rowbase = (size_t)b * L_SEQ + (size_t)lt * 64;
    // 64 rows x 64 d = 1024 float4 loads; 4 per thread; scatter transposed.
    #pragma unroll
    for (int i = 0; i < 4; i++) {
        const int f = tid + i * 256;        // 0..1023
        const int row = f >> 4;             // 0..63
        const int dq  = f & 15;             // float4 index in d
        float4 v = *(const float4*)(qkv + (rowbase + row) * NQKV + h * DH + dq * 4);
        qs[dq * 4 + 0][row] = v.x;
        qs[dq * 4 + 1][row] = v.y;
        qs[dq * 4 + 2][row] = v.z;
        qs[dq * 4 + 3][row] = v.w;
    }
    __syncthreads();

    float acc[4][4];
    float den[4];
    #pragma unroll
    for (int i = 0; i < 4; i++) {
        den[i] = EPSV;
        #pragma unroll
        for (int j = 0; j < 4; j++) acc[i][j] = 0.0f;
    }

    #pragma unroll 8
    for (int k = 0; k < DH; k++) {
        const float ksk = kss[k];
        float4 a0 = *(const float4*)&qs[k][ty * 4];
        float4 bv = *(const float4*)&kvs[k][tx * 4];
        float ar[4] = {a0.x, a0.y, a0.z, a0.w};
        float br[4] = {bv.x, bv.y, bv.z, bv.w};
        #pragma unroll
        for (int i = 0; i < 4; i++) {
            den[i] = fmaf(ar[i], ksk, den[i]);
            #pragma unroll
            for (int j = 0; j < 4; j++)
                acc[i][j] = fmaf(ar[i], br[j], acc[i][j]);
        }
    }

    #pragma unroll
    for (int i = 0; i < 4; i++) {
        const float z = 1.0f / den[i];
        const size_t row = rowbase + ty * 4 + i;
        float4 o;
        o.x = acc[i][0] * z;
        o.y = acc[i][1] * z;
        o.z = acc[i][2] * z;
        o.w = acc[i][3] * z;
        *(float4*)(y + row * DMODEL + h * DH + tx * 4) = o;
    }
}

// ------------------------------------------------------------------
extern "C" void kernel_launch(void* const* d_in, const int* in_sizes, int n_in,
                              void* d_out, int out_size)
{
    const float* x    = (const float*)d_in[0];
    const int*   mask = (const int*)d_in[1];
    const float* Wqkv = (const float*)d_in[2];
    const float* Wout = (const float*)d_in[3];
    float* out = (float*)d_out;

    float* qkv = nullptr;
    float* y   = nullptr;
    cudaGetSymbolAddress((void**)&qkv, g_qkv);
    cudaGetSymbolAddress((void**)&y,   g_y);

    // 1) qkv GEMM (tf32 tensor cores) with phi/mask epilogue
    tgemm_kernel<0><<<dim3(NQKV / 128, MROWS / 128), 256>>>(
        x, Wqkv, qkv, MROWS, NQKV, DMODEL, mask);

    // 2) kv / ksum split-L partials + reduce
    kv_partial_kernel<<<dim3(BATCH * NHEADS, NCHUNK), 256>>>(qkv);
    {
        const int total = BATCH * NHEADS * DH * DH + BATCH * NHEADS * DH;
        kv_reduce_kernel<<<(total + 255) / 256, 256>>>();
    }

    // 3) y = (q @ kv) * z
    apply_kv_kernel<<<dim3(BATCH * NHEADS, L_SEQ / 64), 256>>>(qkv, y);

    // 4) out = (y @ Wout) * mask (tf32 tensor cores)
    tgemm_kernel<1><<<dim3(DMODEL / 128, MROWS / 128), 256>>>(
        y, Wout, out, MROWS, DMODEL, DMODEL, mask);
}

// round 9
// speedup vs baseline: 2.3902x; 1.8708x over previous
#include <cuda_runtime.h>
#include <math.h>
#include <stdint.h>

// Problem constants (fixed shapes from reference)
#define L_SEQ   8192
#define BATCH   4
#define DMODEL  1024
#define NHEADS  16
#define DH      64
#define MROWS   (BATCH * L_SEQ)      // 32768
#define NQKV    (3 * DMODEL)         // 3072
#define EPSV    1e-6f
#define NCHUNK  8                    // L-split chunks for kv reduction

// GEMM pipeline config
#define STAGES   4
#define ASTRIDE  20                  // 16 + 4 pad floats (80B row pitch: 16B-aligned for cp.async,
                                     // and 20*lr+lc mod 32 is conflict-free for fragment LDS)
#define BSTRIDE  132                 // 128 + 4 pad (528B pitch, 16B-aligned)
#define A_STAGE_F (128 * ASTRIDE)    // 2560 floats
#define B_STAGE_F (16 * BSTRIDE)     // 2112 floats
#define SMEM_F   (STAGES * (A_STAGE_F + B_STAGE_F))
#define SMEM_BYTES (SMEM_F * 4)      // 74752 B

// ------------------------------------------------------------------
// Scratch (device globals; no allocation allowed in kernel_launch)
// ------------------------------------------------------------------
__device__ float g_qkv[(size_t)MROWS * NQKV];            // phi(q) | phi(k)*m | v*m
__device__ float g_y[(size_t)MROWS * DMODEL];            // attention output pre-Wout
__device__ float g_kv_part[NCHUNK][BATCH * NHEADS][DH][DH];
__device__ float g_ksum_part[NCHUNK][BATCH * NHEADS][DH];
__device__ float g_kv[BATCH * NHEADS][DH][DH];
__device__ float g_ksum[BATCH * NHEADS][DH];

__device__ __forceinline__ float phi_f(float z) {
    return z > 0.0f ? z + 1.0f : __expf(z);
}

// Round-to-nearest tf32 conversion (unbiased; truncation would bias ~5e-4 over K=1024)
__device__ __forceinline__ unsigned f2tf(float f) {
    unsigned u;
    asm("cvt.rna.tf32.f32 %0, %1;" : "=r"(u) : "f"(f));
    return u;
}

__device__ __forceinline__ void mma_tf32(float* c, const unsigned* a, const unsigned* b) {
    asm volatile(
        "mma.sync.aligned.m16n8k8.row.col.f32.tf32.tf32.f32 "
        "{%0,%1,%2,%3}, {%4,%5,%6,%7}, {%8,%9}, {%0,%1,%2,%3};"
        : "+f"(c[0]), "+f"(c[1]), "+f"(c[2]), "+f"(c[3])
        : "r"(a[0]), "r"(a[1]), "r"(a[2]), "r"(a[3]), "r"(b[0]), "r"(b[1]));
}

__device__ __forceinline__ void cp_async16(void* smem_ptr, const void* gmem_ptr) {
    unsigned saddr = (unsigned)__cvta_generic_to_shared(smem_ptr);
    asm volatile("cp.async.cg.shared.global [%0], [%1], 16;" :: "r"(saddr), "l"(gmem_ptr));
}
__device__ __forceinline__ void cp_commit() {
    asm volatile("cp.async.commit_group;");
}
template <int N>
__device__ __forceinline__ void cp_wait() {
    asm volatile("cp.async.wait_group %0;" :: "n"(N));
}

// ------------------------------------------------------------------
// TF32 tensor-core GEMM v2: cp.async 4-stage pipeline.
// C[M,N] = A[M,K] @ B[K,N] row-major. Block 128x128, BK=16, 256 thr = 8 warps.
// Warp tile 64x32 (4 mt x 4 nt of m16n8k8). Raw f32 staged in smem;
// cvt.rna.tf32 at fragment-load time.
// EPI 0: qkv epilogue (col segment 0: phi ; 1: phi*mask ; 2: *mask)
// EPI 1: out epilogue (*mask[row])
// ------------------------------------------------------------------
template <int EPI>
__global__ __launch_bounds__(256, 2)
void tgemm_kernel(const float* __restrict__ A, const float* __restrict__ B,
                  float* __restrict__ C, int M, int N, int K,
                  const int* __restrict__ mask)
{
    extern __shared__ float sm[];
    float* const Asm = sm;                        // [STAGES][128][ASTRIDE]
    float* const Bsm = sm + STAGES * A_STAGE_F;   // [STAGES][16][BSTRIDE]

    const int tid  = threadIdx.x;
    const int warp = tid >> 5;
    const int lane = tid & 31;
    const int wm   = warp >> 2;      // 0..1
    const int wn   = warp & 3;       // 0..3
    const int lr   = lane >> 2;      // 0..7
    const int lc   = lane & 3;       // 0..3

    const int bm = blockIdx.y * 128;
    const int bn = blockIdx.x * 128;

    // cp.async mappings (2 A granules + 2 B granules per thread per stage)
    const int am0 = tid >> 2;             // A row 0..63 (+64)
    const int ak0 = (tid & 3) << 2;       // A col 0,4,8,12
    const int bk0 = tid >> 5;             // B row 0..7 (+8)
    const int bn0 = (tid & 31) << 2;      // B col 0..124

    const float* Abase = A + (size_t)bm * K;
    const float* Bbase = B + bn;

    const int NT = K >> 4;

    // Prologue: issue stages 0..STAGES-2
    #pragma unroll
    for (int s = 0; s < STAGES - 1; s++) {
        float* As = Asm + s * A_STAGE_F;
        float* Bs = Bsm + s * B_STAGE_F;
        const int k0 = s * 16;
        cp_async16(&As[am0 * ASTRIDE + ak0],
                   Abase + (size_t)am0 * K + k0 + ak0);
        cp_async16(&As[(am0 + 64) * ASTRIDE + ak0],
                   Abase + (size_t)(am0 + 64) * K + k0 + ak0);
        cp_async16(&Bs[bk0 * BSTRIDE + bn0],
                   Bbase + (size_t)(k0 + bk0) * N + bn0);
        cp_async16(&Bs[(bk0 + 8) * BSTRIDE + bn0],
                   Bbase + (size_t)(k0 + bk0 + 8) * N + bn0);
        cp_commit();
    }

    float acc[4][4][4];
    #pragma unroll
    for (int mt = 0; mt < 4; mt++)
        #pragma unroll
        for (int nt = 0; nt < 4; nt++)
            #pragma unroll
            for (int e = 0; e < 4; e++) acc[mt][nt][e] = 0.0f;

    for (int t = 0; t < NT; t++) {
        cp_wait<STAGES - 2>();       // stage t resident
        __syncthreads();

        const int cur = t & (STAGES - 1);
        const float* As = Asm + cur * A_STAGE_F;
        const float* Bs = Bsm + cur * B_STAGE_F;

        #pragma unroll
        for (int ks = 0; ks < 2; ks++) {
            const int c0 = ks * 8 + lc;
            unsigned af[4][4];
            unsigned bf[4][2];
            #pragma unroll
            for (int mt = 0; mt < 4; mt++) {
                const int m0 = wm * 64 + mt * 16 + lr;
                af[mt][0] = f2tf(As[m0 * ASTRIDE + c0]);
                af[mt][1] = f2tf(As[(m0 + 8) * ASTRIDE + c0]);
                af[mt][2] = f2tf(As[m0 * ASTRIDE + c0 + 4]);
                af[mt][3] = f2tf(As[(m0 + 8) * ASTRIDE + c0 + 4]);
            }
            #pragma unroll
            for (int nt = 0; nt < 4; nt++) {
                const int n0 = wn * 32 + nt * 8 + lr;
                bf[nt][0] = f2tf(Bs[c0 * BSTRIDE + n0]);
                bf[nt][1] = f2tf(Bs[(c0 + 4) * BSTRIDE + n0]);
            }
            #pragma unroll
            for (int mt = 0; mt < 4; mt++)
                #pragma unroll
                for (int nt = 0; nt < 4; nt++)
                    mma_tf32(acc[mt][nt], af[mt], bf[nt]);
        }

        // Issue stage t+STAGES-1 into the slot freed at t-1 (safe: the
        // syncthreads above ordered all warps past compute(t-1)).
        const int tf = t + STAGES - 1;
        if (tf < NT) {
            const int s = tf & (STAGES - 1);
            float* Aw = Asm + s * A_STAGE_F;
            float* Bw = Bsm + s * B_STAGE_F;
            const int k0 = tf * 16;
            cp_async16(&Aw[am0 * ASTRIDE + ak0],
                       Abase + (size_t)am0 * K + k0 + ak0);
            cp_async16(&Aw[(am0 + 64) * ASTRIDE + ak0],
                       Abase + (size_t)(am0 + 64) * K + k0 + ak0);
            cp_async16(&Bw[bk0 * BSTRIDE + bn0],
                       Bbase + (size_t)(k0 + bk0) * N + bn0);
            cp_async16(&Bw[(bk0 + 8) * BSTRIDE + bn0],
                       Bbase + (size_t)(k0 + bk0 + 8) * N + bn0);
        }
        cp_commit();                 // commit even if empty: keeps group count aligned
        __syncthreads();             // all warps done reading stage t before overwrite next iter
    }

    // Epilogue: block columns [bn, bn+128) lie in one 1024-segment (128 | 1024)
    const int seg = bn >> 10;   // EPI 0: 0=phi, 1=phi*mask, 2=*mask
    #pragma unroll
    for (int mt = 0; mt < 4; mt++) {
        const int r0 = bm + wm * 64 + mt * 16 + lr;
        const float mv0 = (float)mask[r0];
        const float mv1 = (float)mask[r0 + 8];
        #pragma unroll
        for (int nt = 0; nt < 4; nt++) {
            const int c = bn + wn * 32 + nt * 8 + lc * 2;
            float2 v0 = make_float2(acc[mt][nt][0], acc[mt][nt][1]);
            float2 v1 = make_float2(acc[mt][nt][2], acc[mt][nt][3]);
            if (EPI == 0) {
                if (seg == 0) {
                    v0.x = phi_f(v0.x); v0.y = phi_f(v0.y);
                    v1.x = phi_f(v1.x); v1.y = phi_f(v1.y);
                } else if (seg == 1) {
                    v0.x = phi_f(v0.x) * mv0; v0.y = phi_f(v0.y) * mv0;
                    v1.x = phi_f(v1.x) * mv1; v1.y = phi_f(v1.y) * mv1;
                } else {
                    v0.x *= mv0; v0.y *= mv0;
                    v1.x *= mv1; v1.y *= mv1;
                }
            } else {
                v0.x *= mv0; v0.y *= mv0;
                v1.x *= mv1; v1.y *= mv1;
            }
            *(float2*)(C + (size_t)r0 * N + c)       = v0;
            *(float2*)(C + (size_t)(r0 + 8) * N + c) = v1;
        }
    }
}

// ------------------------------------------------------------------
// kv partials: per (b,h,chunk): kv[d][m] += k[l][d]*v[l][m], ksum[d] += k[l][d]
// ------------------------------------------------------------------
__global__ __launch_bounds__(256)
void kv_partial_kernel(const float* __restrict__ qkv)
{
    const int bh    = blockIdx.x;   // 0..63
    const int chunk = blockIdx.y;   // 0..7
    const int b = bh >> 4, h = bh & 15;
    const int tid = threadIdx.x;
    const int tdg = tid >> 4;       // d block (0..15)
    const int tmg = tid & 15;       // m block (0..15)

    __shared__ float ks[32][64];
    __shared__ float vs[32][64];

    float acc[4][4] = {{0.f,0.f,0.f,0.f},{0.f,0.f,0.f,0.f},
                       {0.f,0.f,0.f,0.f},{0.f,0.f,0.f,0.f}};
    float ksacc[4] = {0.f, 0.f, 0.f, 0.f};

    const size_t rowbase = (size_t)b * L_SEQ + (size_t)chunk * 1024;
    const int kcol = DMODEL + h * DH;
    const int vcol = 2 * DMODEL + h * DH;

    const int lrow = tid >> 4;          // 0..15 (+16)
    const int lcol = (tid & 15) << 2;   // 0..60

    for (int l0 = 0; l0 < 1024; l0 += 32) {
        const float* kp = qkv + (rowbase + l0 + lrow) * NQKV + kcol + lcol;
        const float* vp = qkv + (rowbase + l0 + lrow) * NQKV + vcol + lcol;
        float4 k0 = *(const float4*)kp;
        float4 k1 = *(const float4*)(kp + 16 * NQKV);
        float4 v0 = *(const float4*)vp;
        float4 v1 = *(const float4*)(vp + 16 * NQKV);
        __syncthreads();
        *(float4*)&ks[lrow][lcol]      = k0;
        *(float4*)&ks[16 + lrow][lcol] = k1;
        *(float4*)&vs[lrow][lcol]      = v0;
        *(float4*)&vs[16 + lrow][lcol] = v1;
        __syncthreads();
        #pragma unroll
        for (int l = 0; l < 32; l++) {
            float4 kd = *(const float4*)&ks[l][tdg << 2];
            float4 vm = *(const float4*)&vs[l][tmg << 2];
            float kr[4] = {kd.x, kd.y, kd.z, kd.w};
            float vr[4] = {vm.x, vm.y, vm.z, vm.w};
            #pragma unroll
            for (int i = 0; i < 4; i++)
                #pragma unroll
                for (int j = 0; j < 4; j++)
                    acc[i][j] = fmaf(kr[i], vr[j], acc[i][j]);
            if (tmg == 0) {
                #pragma unroll
                for (int i = 0; i < 4; i++) ksacc[i] += kr[i];
            }
        }
    }

    #pragma unroll
    for (int i = 0; i < 4; i++) {
        const int d = (tdg << 2) + i;
        #pragma unroll
        for (int j = 0; j < 4; j++)
            g_kv_part[chunk][bh][d][(tmg << 2) + j] = acc[i][j];
        if (tmg == 0) g_ksum_part[chunk][bh][d] = ksacc[i];
    }
}

__global__ void kv_reduce_kernel()
{
    const int NKV = BATCH * NHEADS * DH * DH;   // 262144
    const int NKS = BATCH * NHEADS * DH;        // 4096
    const int idx = blockIdx.x * blockDim.x + threadIdx.x;
    if (idx < NKV) {
        const float* p = &g_kv_part[0][0][0][0];
        float s = 0.f;
        #pragma unroll
        for (int c = 0; c < NCHUNK; c++) s += p[(size_t)c * NKV + idx];
        (&g_kv[0][0][0])[idx] = s;
    } else if (idx < NKV + NKS) {
        const int e = idx - NKV;
        const float* p = &g_ksum_part[0][0][0];
        float s = 0.f;
        #pragma unroll
        for (int c = 0; c < NCHUNK; c++) s += p[(size_t)c * NKS + e];
        (&g_ksum[0][0])[e] = s;
    }
}

// ------------------------------------------------------------------
// apply_kv: y[64 rows, 64] = (q @ kv) * z per (b,h, 64-row tile).
// 256 threads as 16x16 grid; thread tile 4 rows x 4 cols. 34KB static smem.
// ------------------------------------------------------------------
__global__ __launch_bounds__(256)
void apply_kv_kernel(const float* __restrict__ qkv, float* __restrict__ y)
{
    const int bh = blockIdx.x;   // 0..63
    const int lt = blockIdx.y;   // 0..127 (64-row tiles)
    const int b = bh >> 4, h = bh & 15;
    const int tid = threadIdx.x;
    const int tx = tid & 15;     // col group (4 cols)
    const int ty = tid >> 4;     // row group (4 rows)

    __shared__ float qs[DH][68];     // q transposed [d][row], padded
    __shared__ float kvs[DH][DH];
    __shared__ float kss[DH];

    const float* kvg = &g_kv[bh][0][0];
    #pragma unroll
    for (int i = 0; i < 4; i++) {
        const int f = tid + i * 256;
        ((float4*)&kvs[0][0])[f] = ((const float4*)kvg)[f];
    }
    if (tid < 16)
        ((float4*)&kss[0])[tid] = ((const float4*)&g_ksum[bh][0])[tid];

    const size_t rowbase = (size_t)b * L_SEQ + (size_t)lt * 64;
    #pragma unroll
    for (int i = 0; i < 4; i++) {
        const int f = tid + i * 256;        // 0..1023
        const int row = f >> 4;             // 0..63
        const int dq  = f & 15;             // float4 index in d
        float4 v = *(const float4*)(qkv + (rowbase + row) * NQKV + h * DH + dq * 4);
        qs[dq * 4 + 0][row] = v.x;
        qs[dq * 4 + 1][row] = v.y;
        qs[dq * 4 + 2][row] = v.z;
        qs[dq * 4 + 3][row] = v.w;
    }
    __syncthreads();

    float acc[4][4];
    float den[4];
    #pragma unroll
    for (int i = 0; i < 4; i++) {
        den[i] = EPSV;
        #pragma unroll
        for (int j = 0; j < 4; j++) acc[i][j] = 0.0f;
    }

    #pragma unroll 8
    for (int k = 0; k < DH; k++) {
        const float ksk = kss[k];
        float4 a0 = *(const float4*)&qs[k][ty * 4];
        float4 bv = *(const float4*)&kvs[k][tx * 4];
        float ar[4] = {a0.x, a0.y, a0.z, a0.w};
        float br[4] = {bv.x, bv.y, bv.z, bv.w};
        #pragma unroll
        for (int i = 0; i < 4; i++) {
            den[i] = fmaf(ar[i], ksk, den[i]);
            #pragma unroll
            for (int j = 0; j < 4; j++)
                acc[i][j] = fmaf(ar[i], br[j], acc[i][j]);
        }
    }

    #pragma unroll
    for (int i = 0; i < 4; i++) {
        const float z = 1.0f / den[i];
        const size_t row = rowbase + ty * 4 + i;
        float4 o;
        o.x = acc[i][0] * z;
        o.y = acc[i][1] * z;
        o.z = acc[i][2] * z;
        o.w = acc[i][3] * z;
        *(float4*)(y + row * DMODEL + h * DH + tx * 4) = o;
    }
}

// ------------------------------------------------------------------
extern "C" void kernel_launch(void* const* d_in, const int* in_sizes, int n_in,
                              void* d_out, int out_size)
{
    const float* x    = (const float*)d_in[0];
    const int*   mask = (const int*)d_in[1];
    const float* Wqkv = (const float*)d_in[2];
    const float* Wout = (const float*)d_in[3];
    float* out = (float*)d_out;

    float* qkv = nullptr;
    float* y   = nullptr;
    cudaGetSymbolAddress((void**)&qkv, g_qkv);
    cudaGetSymbolAddress((void**)&y,   g_y);

    // Opt-in to >48KB dynamic smem (idempotent, not an allocation)
    cudaFuncSetAttribute(tgemm_kernel<0>,
                         cudaFuncAttributeMaxDynamicSharedMemorySize, SMEM_BYTES);
    cudaFuncSetAttribute(tgemm_kernel<1>,
                         cudaFuncAttributeMaxDynamicSharedMemorySize, SMEM_BYTES);

    // 1) qkv GEMM (tf32 tensor cores, cp.async pipeline) with phi/mask epilogue
    tgemm_kernel<0><<<dim3(NQKV / 128, MROWS / 128), 256, SMEM_BYTES>>>(
        x, Wqkv, qkv, MROWS, NQKV, DMODEL, mask);

    // 2) kv / ksum split-L partials + reduce
    kv_partial_kernel<<<dim3(BATCH * NHEADS, NCHUNK), 256>>>(qkv);
    {
        const int total = BATCH * NHEADS * DH * DH + BATCH * NHEADS * DH;
        kv_reduce_kernel<<<(total + 255) / 256, 256>>>();
    }

    // 3) y = (q @ kv) * z
    apply_kv_kernel<<<dim3(BATCH * NHEADS, L_SEQ / 64), 256>>>(qkv, y);

    // 4) out = (y @ Wout) * mask (tf32 tensor cores, cp.async pipeline)
    tgemm_kernel<1><<<dim3(DMODEL / 128, MROWS / 128), 256, SMEM_BYTES>>>(
        y, Wout, out, MROWS, DMODEL, DMODEL, mask);
}